// round 11
// baseline (speedup 1.0000x reference)
#include <cuda_runtime.h>
#include <cuda_bf16.h>
#include <cmath>
#include <cstdint>

// ---------------- problem constants ----------------
#define CB   2
#define CT   1024
#define CE   1024
#define CH   16
#define CHD  64
#define CL   8
#define CV   32000
#define CFF  4096
#define MTOK 2048
#define QS   3072   // fused qkv row width

// ---------------- scratch (device globals; no allocation) ----------------
__device__ __align__(128) float g_x  [MTOK * CE];
__device__ __align__(128) float g_qkv[MTOK * QS];
__device__ __align__(128) __nv_bfloat16 g_hh[MTOK * CE],  g_hl[MTOK * CE];
__device__ __align__(128) __nv_bfloat16 g_oh[MTOK * CE],  g_ol[MTOK * CE];
__device__ __align__(128) __nv_bfloat16 g_ffh[MTOK * CFF], g_ffl[MTOK * CFF];
// weights, bf16 hi/lo, transposed to [N][K]
__device__ __align__(128) __nv_bfloat16 g_wqkv_h[CL * QS * CE],  g_wqkv_l[CL * QS * CE];
__device__ __align__(128) __nv_bfloat16 g_wp_h  [CL * CE * CE],  g_wp_l  [CL * CE * CE];
__device__ __align__(128) __nv_bfloat16 g_w1_h  [CL * CFF * CE], g_w1_l  [CL * CFF * CE];
__device__ __align__(128) __nv_bfloat16 g_w2_h  [CL * CE * CFF], g_w2_l  [CL * CE * CFF];
__device__ __align__(128) __nv_bfloat16 g_wh_h  [(size_t)CV * CE], g_wh_l[(size_t)CV * CE];

// ================= baseline-ISA helpers =================
__device__ __forceinline__ uint32_t smem_u32(const void* p) {
    uint32_t a;
    asm("{ .reg .u64 t; cvta.to.shared.u64 t, %1; cvt.u32.u64 %0, t; }" : "=r"(a) : "l"(p));
    return a;
}
__device__ __forceinline__ void cp16(uint32_t saddr, const void* gaddr) {
    asm volatile("cp.async.cg.shared.global [%0], [%1], 16;" :: "r"(saddr), "l"(gaddr));
}
__device__ __forceinline__ void cp_commit() { asm volatile("cp.async.commit_group;"); }
template<int N> __device__ __forceinline__ void cp_wait() {
    asm volatile("cp.async.wait_group %0;" :: "n"(N));
}
__device__ __forceinline__ void ldsm4(uint32_t* r, uint32_t addr) {
    asm volatile("ldmatrix.sync.aligned.m8n8.x4.shared.b16 {%0,%1,%2,%3}, [%4];"
                 : "=r"(r[0]), "=r"(r[1]), "=r"(r[2]), "=r"(r[3]) : "r"(addr));
}
__device__ __forceinline__ void mma16816(float* c, const uint32_t* a, uint32_t b0, uint32_t b1) {
    asm volatile(
        "mma.sync.aligned.m16n8k16.row.col.f32.bf16.bf16.f32 "
        "{%0,%1,%2,%3}, {%4,%5,%6,%7}, {%8,%9}, {%0,%1,%2,%3};"
        : "+f"(c[0]), "+f"(c[1]), "+f"(c[2]), "+f"(c[3])
        : "r"(a[0]), "r"(a[1]), "r"(a[2]), "r"(a[3]), "r"(b0), "r"(b1));
}
__device__ __forceinline__ uint32_t pk2(__nv_bfloat16 a, __nv_bfloat16 b) {
    __nv_bfloat162 t = __halves2bfloat162(a, b);
    return *reinterpret_cast<uint32_t*>(&t);
}
// packed smem addressing: two logical 32-elem (64B) rows per 128B physical row
__device__ __forceinline__ uint32_t packaddr(int row, int u) {
    return (uint32_t)((row >> 1) * 128 + ((((row & 1) * 4 + u) ^ ((row >> 1) & 7)) * 16));
}

// ================= weight conversion: fp32 (K,N) -> bf16 hi/lo (N,K) =================
__global__ void wconv(const float* __restrict__ in, __nv_bfloat16* __restrict__ oh,
                      __nv_bfloat16* __restrict__ ol, int K, int N)
{
    __shared__ float t[32][33];
    const int l = blockIdx.z;
    in += (size_t)l * K * N;
    oh += (size_t)l * N * K;
    ol += (size_t)l * N * K;
    const int k0 = blockIdx.x * 32, n0 = blockIdx.y * 32;
    const int tx = threadIdx.x, ty = threadIdx.y;
#pragma unroll
    for (int j = 0; j < 4; j++)
        t[ty + j * 8][tx] = in[(size_t)(k0 + ty + j * 8) * N + n0 + tx];
    __syncthreads();
#pragma unroll
    for (int j = 0; j < 4; j++) {
        const int n = n0 + ty + j * 8, k = k0 + tx;
        float f = t[tx][ty + j * 8];
        __nv_bfloat16 h = __float2bfloat16(f);
        oh[(size_t)n * K + k] = h;
        ol[(size_t)n * K + k] = __float2bfloat16(f - __bfloat162float(h));
    }
}

// QKV weights (L,H,E,HD) -> fused [l][n=sel*1024+h*64+d][k]
__global__ void wconv_qkv(const float* __restrict__ Wq, const float* __restrict__ Wk,
                          const float* __restrict__ Wv,
                          __nv_bfloat16* __restrict__ oh, __nv_bfloat16* __restrict__ ol)
{
    __shared__ float t[32][33];
    const int l = blockIdx.z;
    const int k0 = blockIdx.x * 32, n0 = blockIdx.y * 32;
    const int sel = n0 >> 10;
    const float* W = (sel == 0) ? Wq : (sel == 1) ? Wk : Wv;
    const int hh = (n0 >> 6) & 15, d0 = n0 & 63;
    const int tx = threadIdx.x, ty = threadIdx.y;
#pragma unroll
    for (int j = 0; j < 4; j++)
        t[ty + j * 8][tx] = W[((size_t)(l * CH + hh) * CE + k0 + ty + j * 8) * CHD + d0 + tx];
    __syncthreads();
    const size_t ob = (size_t)l * QS * CE;
#pragma unroll
    for (int j = 0; j < 4; j++) {
        const int n = n0 + ty + j * 8, k = k0 + tx;
        float f = t[tx][ty + j * 8];
        __nv_bfloat16 h = __float2bfloat16(f);
        oh[ob + (size_t)n * CE + k] = h;
        ol[ob + (size_t)n * CE + k] = __float2bfloat16(f - __bfloat162float(h));
    }
}

// ================= bf16x3 HMMA GEMM, BK=32, 3-stage pipeline =================
// C(M x N=128-col-tiles) = A(MxK) * B(NxK)^T ; bf16 hi/lo pairs, fp32 accum.
// Stage = [Ah ASZ][Al ASZ][Bh 8K][Bl 8K]. TM=128: 32KB/stage; TM=64: 24KB/stage.
// 3 stages -> 96KB / 72KB; 2 CTAs/SM either way.
template<int TM, bool HB, bool RELU, bool HR, bool OB, bool SWAP>
__global__ void __launch_bounds__(256, 2)
mma_gemm(const __nv_bfloat16* __restrict__ Ah, const __nv_bfloat16* __restrict__ Al,
         const __nv_bfloat16* __restrict__ Bh, const __nv_bfloat16* __restrict__ Bl,
         const float* __restrict__ bias, const float* __restrict__ Res,
         float* __restrict__ Cf, __nv_bfloat16* __restrict__ Ch,
         __nv_bfloat16* __restrict__ Cl, int M, int N, int K)
{
    constexpr int ASZ   = TM * 64;            // bytes per A region (h or l)
    constexpr int STAGE = 2 * ASZ + 16384;
    constexpr int MW    = TM / 32;            // m-warps (4 or 2)
    constexpr int WN    = 128 / (8 / MW);     // warp n-tile (64 or 32)
    constexpr int NJ    = WN / 8;             // n-frags per warp (8 or 4)
    constexpr int NG    = NJ / 2;             // b ldsm groups (4 or 2)

    extern __shared__ char smem[];
    const uint32_t sbase = smem_u32(smem);
    const int tid  = threadIdx.x;
    const int lane = tid & 31;
    const int wid  = tid >> 5;
    const int row0 = (SWAP ? blockIdx.x : blockIdx.y) * TM;
    const int col0 = (SWAP ? blockIdx.y : blockIdx.x) * 128;
    const int wm = (wid % MW) * 32;
    const int wn = (wid / MW) * WN;

    // ldmatrix addressing
    const int lrow16 = (lane & 7) + ((lane >> 3) & 1) * 8;   // 0..15
    const uint32_t rowoff = (uint32_t)(lrow16 >> 1) * 128;
    const uint32_t px = (uint32_t)(lrow16 >> 1);
    const uint32_t hs = (uint32_t)(lrow16 & 1) * 4;
    const uint32_t khalf = (uint32_t)(lane >> 4);
    const uint32_t aBase = (uint32_t)((wm >> 1) * 128) + rowoff;
    const uint32_t bBase = (uint32_t)((wn >> 1) * 128) + rowoff;

    float acc[2][NJ][4];
#pragma unroll
    for (int mi = 0; mi < 2; mi++)
#pragma unroll
        for (int j = 0; j < NJ; j++)
#pragma unroll
            for (int c = 0; c < 4; c++) acc[mi][j][c] = 0.f;

    const int NS = K >> 5;

    // ---- stage loader ----
    auto load_stage = [&](int s, uint32_t dst) {
        const int ke = s << 5;
#pragma unroll
        for (int idx = tid; idx < TM * 4; idx += 256) {
            const int row = idx >> 2, u = idx & 3;
            const uint32_t sa = packaddr(row, u);
            const size_t go = (size_t)(row0 + row) * K + ke + u * 8;
            cp16(dst + sa,       Ah + go);
            cp16(dst + ASZ + sa, Al + go);
        }
#pragma unroll
        for (int idx = tid; idx < 512; idx += 256) {
            const int row = idx >> 2, u = idx & 3;
            const uint32_t sa = packaddr(row, u);
            const size_t go = (size_t)(col0 + row) * K + ke + u * 8;
            cp16(dst + 2 * ASZ + sa,        Bh + go);
            cp16(dst + 2 * ASZ + 8192 + sa, Bl + go);
        }
    };

    // prologue: stages 0, 1
    load_stage(0, sbase);              cp_commit();
    load_stage(1, sbase + STAGE);      cp_commit();

    for (int s = 0; s < NS; s++) {
        if (s + 2 < NS) {
            const int b = (s + 2) % 3;
            load_stage(s + 2, sbase + (uint32_t)(b * STAGE));
        }
        cp_commit();          // possibly-empty group keeps indices aligned
        cp_wait<2>();         // stage s guaranteed complete
        __syncthreads();

        const uint32_t tb = sbase + (uint32_t)((s % 3) * STAGE);
#pragma unroll
        for (int kb = 0; kb < 2; kb++) {
            const uint32_t cu = (uint32_t)(kb * 2) + khalf;
            const uint32_t ucol = ((hs + cu) ^ px) * 16;
            uint32_t ahf[2][4], alf[2][4], bhf[NG][4], blf[NG][4];
#pragma unroll
            for (int mi = 0; mi < 2; mi++) {
                const uint32_t ao = aBase + (uint32_t)(mi * 8 * 128) + ucol;
                ldsm4(ahf[mi], tb + ao);
                ldsm4(alf[mi], tb + ASZ + ao);
            }
#pragma unroll
            for (int g = 0; g < NG; g++) {
                const uint32_t bo = bBase + (uint32_t)(g * 8 * 128) + ucol;
                ldsm4(bhf[g], tb + 2 * ASZ + bo);
                ldsm4(blf[g], tb + 2 * ASZ + 8192 + bo);
            }
#pragma unroll
            for (int mi = 0; mi < 2; mi++)
#pragma unroll
                for (int j = 0; j < NJ; j++) {
                    const int g = j >> 1, ss = j & 1;
                    mma16816(acc[mi][j], ahf[mi], bhf[g][ss], bhf[g][2 + ss]);
                    mma16816(acc[mi][j], ahf[mi], blf[g][ss], blf[g][2 + ss]);
                    mma16816(acc[mi][j], alf[mi], bhf[g][ss], bhf[g][2 + ss]);
                }
        }
        __syncthreads();
    }

    // ---- epilogue ----
    const int r  = lane >> 2;
    const int cc = (lane & 3) * 2;
#pragma unroll
    for (int mi = 0; mi < 2; mi++)
#pragma unroll
        for (int hh = 0; hh < 2; hh++) {
            const int m = row0 + wm + mi * 16 + r + hh * 8;
#pragma unroll
            for (int j = 0; j < NJ; j++) {
                const int n = col0 + wn + j * 8 + cc;
                float v0 = acc[mi][j][hh * 2 + 0];
                float v1 = acc[mi][j][hh * 2 + 1];
                if (HB) { v0 += bias[n]; v1 += bias[n + 1]; }
                if (HR) {
                    const float2 rr = *reinterpret_cast<const float2*>(Res + (size_t)m * N + n);
                    v0 += rr.x; v1 += rr.y;
                }
                if (RELU) { v0 = fmaxf(v0, 0.f); v1 = fmaxf(v1, 0.f); }
                if (OB) {
                    __nv_bfloat16 h0 = __float2bfloat16(v0), h1 = __float2bfloat16(v1);
                    *reinterpret_cast<uint32_t*>(Ch + (size_t)m * N + n) = pk2(h0, h1);
                    *reinterpret_cast<uint32_t*>(Cl + (size_t)m * N + n) =
                        pk2(__float2bfloat16(v0 - __bfloat162float(h0)),
                            __float2bfloat16(v1 - __bfloat162float(h1)));
                } else {
                    *reinterpret_cast<float2*>(Cf + (size_t)m * N + n) = make_float2(v0, v1);
                }
            }
        }
}

// ---------------- embedding ----------------
__global__ void embed_kernel(const int* __restrict__ idx,
                             const float* __restrict__ tok,
                             const float* __restrict__ pos,
                             float* __restrict__ x)
{
    int bt = blockIdx.x;
    int t  = bt % CT;
    int tokid = idx[bt];
    const float4* te = reinterpret_cast<const float4*>(tok + (size_t)tokid * CE);
    const float4* pe = reinterpret_cast<const float4*>(pos + (size_t)t * CE);
    float4* xo = reinterpret_cast<float4*>(x + (size_t)bt * CE);
    for (int i = threadIdx.x; i < CE / 4; i += blockDim.x) {
        float4 a = te[i], p = pe[i];
        a.x += p.x; a.y += p.y; a.z += p.z; a.w += p.w;
        xo[i] = a;
    }
}

// ---------------- LayerNorm over T axis (quirk), ddof=1; writes bf16 hi/lo ----------------
__global__ void __launch_bounds__(1024) ln_kernel(
    const float* __restrict__ x, const float* __restrict__ g,
    const float* __restrict__ bvec,
    __nv_bfloat16* __restrict__ oh, __nv_bfloat16* __restrict__ ol)
{
    int b  = blockIdx.y;
    int e  = blockIdx.x * 32 + threadIdx.x;
    int ty = threadIdx.y;
    const float* xb = x + (size_t)b * CT * CE;

    float vals[32];
    float s = 0.f, s2 = 0.f;
#pragma unroll
    for (int i = 0; i < 32; i++) {
        float v = xb[(size_t)(ty + i * 32) * CE + e];
        vals[i] = v; s += v; s2 += v * v;
    }
    __shared__ float sh1[32][33];
    __shared__ float sh2[32][33];
    sh1[ty][threadIdx.x] = s;
    sh2[ty][threadIdx.x] = s2;
    __syncthreads();
#pragma unroll
    for (int off = 16; off > 0; off >>= 1) {
        if (ty < off) {
            sh1[ty][threadIdx.x] += sh1[ty + off][threadIdx.x];
            sh2[ty][threadIdx.x] += sh2[ty + off][threadIdx.x];
        }
        __syncthreads();
    }
    float mean = sh1[0][threadIdx.x] * (1.0f / CT);
    float var  = (sh2[0][threadIdx.x] - (float)CT * mean * mean) * (1.0f / (CT - 1));
    float inv  = rsqrtf(var + 1e-5f);
    float gg = g[e], bb = bvec[e];
    const size_t ob = (size_t)b * CT * CE;
#pragma unroll
    for (int i = 0; i < 32; i++) {
        float f = gg * (vals[i] - mean) * inv + bb;
        __nv_bfloat16 hv = __float2bfloat16(f);
        size_t idx = ob + (size_t)(ty + i * 32) * CE + e;
        oh[idx] = hv;
        ol[idx] = __float2bfloat16(f - __bfloat162float(hv));
    }
}

// ---------------- fused causal attention (flash-style), NO 1/sqrt(d) scale ----------------
__global__ void __launch_bounds__(256) attn_kernel(
    const float* __restrict__ QKV,
    __nv_bfloat16* __restrict__ Oh, __nv_bfloat16* __restrict__ Ol)
{
    const int mi  = blockIdx.x;
    const int h   = blockIdx.y;
    const int b   = blockIdx.z;
    const int tid = threadIdx.x;
    const int tx  = tid & 15;
    const int ty  = tid >> 4;
    const int r0  = ty * 4;
    const int c0  = tx * 4;
    const int m0  = mi * 64;
    const size_t base = ((size_t)b * CT) * QS + (size_t)h * CHD;

    __shared__ float Qs[64][64];
    __shared__ float Kt[64][64];
    __shared__ float Vs[64][64];

    {
        int lr = tid >> 2;
        int lc = (tid & 3) * 4;
#pragma unroll
        for (int j = 0; j < 4; j++) {
            int d = lc + j * 16;
            float4 qv = *reinterpret_cast<const float4*>(&QKV[base + (size_t)(m0 + lr) * QS + d]);
            Qs[lr][d] = qv.x; Qs[lr][d + 1] = qv.y; Qs[lr][d + 2] = qv.z; Qs[lr][d + 3] = qv.w;
        }
    }

    float m_run[4], l_run[4], o_acc[4][4];
#pragma unroll
    for (int a = 0; a < 4; a++) {
        m_run[a] = -INFINITY; l_run[a] = 0.f;
#pragma unroll
        for (int j = 0; j < 4; j++) o_acc[a][j] = 0.f;
    }

    for (int nt = 0; nt <= mi; nt++) {
        __syncthreads();
        const int n0 = nt * 64;
        {
            int lr = tid >> 2;
            int lc = (tid & 3) * 4;
#pragma unroll
            for (int j = 0; j < 4; j++) {
                int d = lc + j * 16;
                float4 kv = *reinterpret_cast<const float4*>(
                    &QKV[base + 1024 + (size_t)(n0 + lr) * QS + d]);
                Kt[d][lr] = kv.x; Kt[d + 1][lr] = kv.y; Kt[d + 2][lr] = kv.z; Kt[d + 3][lr] = kv.w;
                float4 vv = *reinterpret_cast<const float4*>(
                    &QKV[base + 2048 + (size_t)(n0 + lr) * QS + d]);
                Vs[lr][d] = vv.x; Vs[lr][d + 1] = vv.y; Vs[lr][d + 2] = vv.z; Vs[lr][d + 3] = vv.w;
            }
        }
        __syncthreads();

        float s[4][4];
#pragma unroll
        for (int a = 0; a < 4; a++)
#pragma unroll
            for (int j = 0; j < 4; j++) s[a][j] = 0.f;
#pragma unroll
        for (int k = 0; k < 64; k++) {
            float qa[4], kb[4];
#pragma unroll
            for (int a = 0; a < 4; a++) qa[a] = Qs[r0 + a][k];
#pragma unroll
            for (int j = 0; j < 4; j++) kb[j] = Kt[k][c0 + j];
#pragma unroll
            for (int a = 0; a < 4; a++)
#pragma unroll
                for (int j = 0; j < 4; j++)
                    s[a][j] = fmaf(qa[a], kb[j], s[a][j]);
        }
        if (nt == mi) {
#pragma unroll
            for (int a = 0; a < 4; a++)
#pragma unroll
                for (int j = 0; j < 4; j++)
                    if ((r0 + a) < (c0 + j)) s[a][j] = -INFINITY;
        }

        float p[4][4];
#pragma unroll
        for (int a = 0; a < 4; a++) {
            float mx = fmaxf(fmaxf(s[a][0], s[a][1]), fmaxf(s[a][2], s[a][3]));
#pragma unroll
            for (int off = 1; off < 16; off <<= 1)
                mx = fmaxf(mx, __shfl_xor_sync(0xffffffffu, mx, off));
            float m_new = fmaxf(m_run[a], mx);
            float scale = expf(m_run[a] - m_new);
            float rs = 0.f;
#pragma unroll
            for (int j = 0; j < 4; j++) {
                float e = expf(s[a][j] - m_new);
                p[a][j] = e; rs += e;
            }
#pragma unroll
            for (int off = 1; off < 16; off <<= 1)
                rs += __shfl_xor_sync(0xffffffffu, rs, off);
            l_run[a] = l_run[a] * scale + rs;
            m_run[a] = m_new;
#pragma unroll
            for (int j = 0; j < 4; j++) o_acc[a][j] *= scale;
        }
        __syncthreads();
#pragma unroll
        for (int a = 0; a < 4; a++)
#pragma unroll
            for (int j = 0; j < 4; j++)
                Kt[r0 + a][c0 + j] = p[a][j];
        __syncthreads();

#pragma unroll
        for (int k = 0; k < 64; k++) {
            float pa[4], vb[4];
#pragma unroll
            for (int a = 0; a < 4; a++) pa[a] = Kt[r0 + a][k];
#pragma unroll
            for (int j = 0; j < 4; j++) vb[j] = Vs[k][c0 + j];
#pragma unroll
            for (int a = 0; a < 4; a++)
#pragma unroll
                for (int j = 0; j < 4; j++)
                    o_acc[a][j] = fmaf(pa[a], vb[j], o_acc[a][j]);
        }
    }

#pragma unroll
    for (int a = 0; a < 4; a++) {
        float invl = 1.f / l_run[a];
        float o0 = o_acc[a][0] * invl, o1 = o_acc[a][1] * invl;
        float o2 = o_acc[a][2] * invl, o3 = o_acc[a][3] * invl;
        __nv_bfloat16 h0 = __float2bfloat16(o0), h1 = __float2bfloat16(o1);
        __nv_bfloat16 h2 = __float2bfloat16(o2), h3 = __float2bfloat16(o3);
        size_t oidx = ((size_t)(b * CT + m0 + r0 + a)) * CE + h * CHD + c0;
        *reinterpret_cast<uint2*>(Oh + oidx) = make_uint2(pk2(h0, h1), pk2(h2, h3));
        *reinterpret_cast<uint2*>(Ol + oidx) = make_uint2(
            pk2(__float2bfloat16(o0 - __bfloat162float(h0)),
                __float2bfloat16(o1 - __bfloat162float(h1))),
            pk2(__float2bfloat16(o2 - __bfloat162float(h2)),
                __float2bfloat16(o3 - __bfloat162float(h3))));
    }
}

// ---------------- launcher ----------------
extern "C" void kernel_launch(void* const* d_in, const int* in_sizes, int n_in,
                              void* d_out, int out_size)
{
    (void)in_sizes; (void)n_in; (void)out_size;
    const int*   idx     = (const int*)  d_in[0];
    const float* tok_emb = (const float*)d_in[1];
    const float* pos_emb = (const float*)d_in[2];
    const float* Wq      = (const float*)d_in[3];
    const float* Wk      = (const float*)d_in[4];
    const float* Wv      = (const float*)d_in[5];
    const float* projW   = (const float*)d_in[6];
    const float* projb   = (const float*)d_in[7];
    const float* ln1g    = (const float*)d_in[8];
    const float* ln1b    = (const float*)d_in[9];
    const float* ln2g    = (const float*)d_in[10];
    const float* ln2b    = (const float*)d_in[11];
    const float* W1      = (const float*)d_in[12];
    const float* b1      = (const float*)d_in[13];
    const float* W2      = (const float*)d_in[14];
    const float* b2      = (const float*)d_in[15];
    const float* lnfg    = (const float*)d_in[16];
    const float* lnfb    = (const float*)d_in[17];
    const float* headW   = (const float*)d_in[18];
    const float* headb   = (const float*)d_in[19];
    float* out = (float*)d_out;

    float *x, *qkv;
    __nv_bfloat16 *hh, *hl, *oh, *ol, *ffh, *ffl;
    __nv_bfloat16 *wqkvh, *wqkvl, *wph, *wpl, *w1h, *w1l, *w2h, *w2l, *whh, *whl;
    cudaGetSymbolAddress((void**)&x,    g_x);
    cudaGetSymbolAddress((void**)&qkv,  g_qkv);
    cudaGetSymbolAddress((void**)&hh,   g_hh);
    cudaGetSymbolAddress((void**)&hl,   g_hl);
    cudaGetSymbolAddress((void**)&oh,   g_oh);
    cudaGetSymbolAddress((void**)&ol,   g_ol);
    cudaGetSymbolAddress((void**)&ffh,  g_ffh);
    cudaGetSymbolAddress((void**)&ffl,  g_ffl);
    cudaGetSymbolAddress((void**)&wqkvh, g_wqkv_h);
    cudaGetSymbolAddress((void**)&wqkvl, g_wqkv_l);
    cudaGetSymbolAddress((void**)&wph,  g_wp_h);
    cudaGetSymbolAddress((void**)&wpl,  g_wp_l);
    cudaGetSymbolAddress((void**)&w1h,  g_w1_h);
    cudaGetSymbolAddress((void**)&w1l,  g_w1_l);
    cudaGetSymbolAddress((void**)&w2h,  g_w2_h);
    cudaGetSymbolAddress((void**)&w2l,  g_w2_l);
    cudaGetSymbolAddress((void**)&whh,  g_wh_h);
    cudaGetSymbolAddress((void**)&whl,  g_wh_l);

    const int SM128 = 3 * 32768;   // 96KB
    const int SM64  = 3 * 24576;   // 72KB
    cudaFuncSetAttribute(mma_gemm<128, false, false, false, false, false>,
                         cudaFuncAttributeMaxDynamicSharedMemorySize, SM128);
    cudaFuncSetAttribute(mma_gemm<128, true, true, false, true, false>,
                         cudaFuncAttributeMaxDynamicSharedMemorySize, SM128);
    cudaFuncSetAttribute(mma_gemm<128, true, false, false, false, true>,
                         cudaFuncAttributeMaxDynamicSharedMemorySize, SM128);
    cudaFuncSetAttribute(mma_gemm<64, true, false, true, false, false>,
                         cudaFuncAttributeMaxDynamicSharedMemorySize, SM64);

    const dim3 lnGrid(CE / 32, CB), lnBlk(32, 32);
    const dim3 gQKV(QS / 128, MTOK / 128);        // (24,16) = 384
    const dim3 gE64(CE / 128, MTOK / 64);         // (8,32)  = 256 (TM=64)
    const dim3 gFF (CFF / 128, MTOK / 128);       // (32,16) = 512
    const dim3 gV  (MTOK / 128, CV / 128);        // swapped (16,250)
    const dim3 gAttn(CT / 64, CH, CB);
    const dim3 cblk(32, 8);

    // Layer 0 interleaved with weight conversion (keeps ncu sample on a GEMM)
    embed_kernel<<<MTOK, 256>>>(idx, tok_emb, pos_emb, x);
    wconv_qkv<<<dim3(CE / 32, QS / 32, CL), cblk>>>(Wq, Wk, Wv, wqkvh, wqkvl);
    ln_kernel<<<lnGrid, lnBlk>>>(x, ln1g, ln1b, hh, hl);
    mma_gemm<128, false, false, false, false, false><<<gQKV, 256, SM128>>>(
        hh, hl, wqkvh, wqkvl, nullptr, nullptr, qkv, nullptr, nullptr, MTOK, QS, CE);
    attn_kernel<<<gAttn, 256>>>(qkv, oh, ol);
    wconv<<<dim3(CE / 32, CE / 32, CL), cblk>>>(projW, wph, wpl, CE, CE);
    mma_gemm<64, true, false, true, false, false><<<gE64, 256, SM64>>>(
        oh, ol, wph, wpl, projb, x, x, nullptr, nullptr, MTOK, CE, CE);
    wconv<<<dim3(CE / 32, CFF / 32, CL), cblk>>>(W1, w1h, w1l, CE, CFF);
    ln_kernel<<<lnGrid, lnBlk>>>(x, ln2g, ln2b, hh, hl);
    mma_gemm<128, true, true, false, true, false><<<gFF, 256, SM128>>>(
        hh, hl, w1h, w1l, b1, nullptr, nullptr, ffh, ffl, MTOK, CFF, CE);
    wconv<<<dim3(CFF / 32, CE / 32, CL), cblk>>>(W2, w2h, w2l, CFF, CE);
    mma_gemm<64, true, false, true, false, false><<<gE64, 256, SM64>>>(
        ffh, ffl, w2h, w2l, b2, x, x, nullptr, nullptr, MTOK, CE, CFF);
    wconv<<<dim3(CE / 32, CV / 32, 1), cblk>>>(headW, whh, whl, CE, CV);

    for (int l = 1; l < CL; l++) {
        ln_kernel<<<lnGrid, lnBlk>>>(x, ln1g + l * CE, ln1b + l * CE, hh, hl);
        mma_gemm<128, false, false, false, false, false><<<gQKV, 256, SM128>>>(
            hh, hl, wqkvh + (size_t)l * QS * CE, wqkvl + (size_t)l * QS * CE,
            nullptr, nullptr, qkv, nullptr, nullptr, MTOK, QS, CE);
        attn_kernel<<<gAttn, 256>>>(qkv, oh, ol);
        mma_gemm<64, true, false, true, false, false><<<gE64, 256, SM64>>>(
            oh, ol, wph + (size_t)l * CE * CE, wpl + (size_t)l * CE * CE,
            projb + l * CE, x, x, nullptr, nullptr, MTOK, CE, CE);
        ln_kernel<<<lnGrid, lnBlk>>>(x, ln2g + l * CE, ln2b + l * CE, hh, hl);
        mma_gemm<128, true, true, false, true, false><<<gFF, 256, SM128>>>(
            hh, hl, w1h + (size_t)l * CFF * CE, w1l + (size_t)l * CFF * CE,
            b1 + l * CFF, nullptr, nullptr, ffh, ffl, MTOK, CFF, CE);
        mma_gemm<64, true, false, true, false, false><<<gE64, 256, SM64>>>(
            ffh, ffl, w2h + (size_t)l * CE * CFF, w2l + (size_t)l * CE * CFF,
            b2 + l * CE, x, x, nullptr, nullptr, MTOK, CE, CFF);
    }

    ln_kernel<<<lnGrid, lnBlk>>>(x, lnfg, lnfb, hh, hl);
    mma_gemm<128, true, false, false, false, true><<<gV, 256, SM128>>>(
        hh, hl, whh, whl, headb, nullptr, out, nullptr, nullptr, MTOK, CV, CE);
}